// round 5
// baseline (speedup 1.0000x reference)
#include <cuda_runtime.h>

#define SZ 256
#define NCH 8
#define NPIX (SZ*SZ)
#define WPR (SZ/32)   // words per row = 8
#define BOXR 7
#define BOXR2 (BOXR*BOXR)

// Per-channel occupancy bitmasks: 8 channels x 256 rows x 8 words = 64KB
__device__ unsigned int g_maskbits[NCH * SZ * WPR];

__global__ void build_masks_kernel(const int* __restrict__ lookup) {
    int y = blockIdx.x;
    int x = threadIdx.x;
    int v = lookup[y * SZ + x];
    int w = x >> 5;
    #pragma unroll
    for (int c = 0; c < NCH; ++c) {
        unsigned int mk = __ballot_sync(0xFFFFFFFFu, v == c + 1);
        if ((x & 31) == 0)
            g_maskbits[(c * SZ + y) * WPR + w] = mk;
    }
}

__global__ __launch_bounds__(256) void knn_fill_kernel(
    const float* __restrict__ img, const int* __restrict__ lookup,
    float* __restrict__ out)
{
    const int c  = blockIdx.y;   // channel 0..7
    const int y0 = blockIdx.x;   // row
    const int x0 = threadIdx.x;  // col

    __shared__ unsigned int m[SZ * WPR];  // 8KB channel bitmask
    #pragma unroll
    for (int i = 0; i < 8; ++i)
        m[i * 256 + threadIdx.x] = g_maskbits[c * SZ * WPR + i * 256 + threadIdx.x];
    __syncthreads();

    const int pix = y0 * SZ + x0;

    if (__ldg(&lookup[pix]) == c + 1) {
        out[c * NPIX + pix] = __ldg(&img[pix]);   // filled pixel keeps its value
        return;
    }

    // ---- Phase 1: fixed 15x15 Chebyshev box, 32-bit keys (d2<<16)|idx ----
    // Inside the box d2 <= 2*49 = 98 < 2^16, idx < 2^16 -> 32-bit key,
    // ascending order == top_k order (smallest d2, ties -> smallest idx).
    unsigned int k0 = ~0u, k1 = ~0u, k2 = ~0u, k3 = ~0u;

    auto ins32 = [&](unsigned int key) {
        if (key < k3) {
            k3 = key;
            if (k3 < k2) {
                unsigned int t = k2; k2 = k3; k3 = t;
                if (k2 < k1) {
                    t = k1; k1 = k2; k2 = t;
                    if (k1 < k0) { t = k0; k0 = k1; k1 = t; }
                }
            }
        }
    };

    {
        int xlo = x0 - BOXR; if (xlo < 0) xlo = 0;
        int xhi = x0 + BOXR; if (xhi > SZ - 1) xhi = SZ - 1;
        int ylo = y0 - BOXR; if (ylo < 0) ylo = 0;
        int yhi = y0 + BOXR; if (yhi > SZ - 1) yhi = SZ - 1;
        const int wl = xlo >> 5, wh = xhi >> 5;
        const unsigned int mlo = 0xFFFFFFFFu << (xlo & 31);
        const unsigned int mhi = 0xFFFFFFFFu >> (31 - (xhi & 31));

        for (int yy = ylo; yy <= yhi; ++yy) {
            int dy = yy - y0;
            unsigned int base = ((unsigned int)(dy * dy) << 16) + (unsigned int)(yy << 8);
            const unsigned int* row = &m[yy << 3];
            unsigned int w0 = row[wl] & mlo;
            if (wl == wh) {
                w0 &= mhi;
                int xb = wl << 5;
                while (w0) {
                    int b = __ffs(w0) - 1; w0 &= w0 - 1;
                    int x = xb + b, dx = x - x0;
                    ins32(base + ((unsigned int)(dx * dx) << 16) + x);
                }
            } else {
                unsigned int w1 = row[wh] & mhi;
                int xb0 = wl << 5, xb1 = wh << 5;
                while (w0) {
                    int b = __ffs(w0) - 1; w0 &= w0 - 1;
                    int x = xb0 + b, dx = x - x0;
                    ins32(base + ((unsigned int)(dx * dx) << 16) + x);
                }
                while (w1) {
                    int b = __ffs(w1) - 1; w1 &= w1 - 1;
                    int x = xb1 + b, dx = x - x0;
                    ins32(base + ((unsigned int)(dx * dx) << 16) + x);
                }
            }
        }
    }

    unsigned int ridx[4];
    unsigned int rd2[4];

    if (k3 != ~0u && (k3 >> 16) <= (unsigned int)BOXR2) {
        // Exact: every unscanned cell has Chebyshev >= 8 -> d2 >= 64 > 49 >= d2_4,
        // strictly greater, so it cannot enter the top-4 even on ties.
        ridx[0] = k0 & 0xFFFFu; rd2[0] = k0 >> 16;
        ridx[1] = k1 & 0xFFFFu; rd2[1] = k1 >> 16;
        ridx[2] = k2 & 0xFFFFu; rd2[2] = k2 >> 16;
        ridx[3] = k3 & 0xFFFFu; rd2[3] = k3 >> 16;
    } else {
        // ---- Rare fallback (~1e-5 of pixels): exact expanding ring search ----
        unsigned long long b0 = ~0ULL, b1 = ~0ULL, b2 = ~0ULL, b3 = ~0ULL;
        int found = 0;

        auto visit = [&](int yy, int xx) {
            if ((unsigned)yy >= SZ || (unsigned)xx >= SZ) return;
            unsigned int word = m[(yy << 3) + (xx >> 5)];
            if ((word >> (xx & 31)) & 1u) {
                int dy = yy - y0, dx = xx - x0;
                unsigned int d2 = (unsigned int)(dy * dy + dx * dx);
                unsigned long long key =
                    ((unsigned long long)d2 << 16) | (unsigned int)((yy << 8) + xx);
                ++found;
                if (key < b3) {
                    b3 = key;
                    if (b3 < b2) {
                        unsigned long long t = b2; b2 = b3; b3 = t;
                        if (b2 < b1) {
                            t = b1; b1 = b2; b2 = t;
                            if (b1 < b0) { t = b0; b0 = b1; b1 = t; }
                        }
                    }
                }
            }
        };

        for (int r = 1; r < SZ; ++r) {
            if (found >= 4 && (unsigned int)(r * r) > (unsigned int)(b3 >> 16)) break;
            int yt = y0 - r, yb = y0 + r;
            for (int xx = x0 - r; xx <= x0 + r; ++xx) { visit(yt, xx); visit(yb, xx); }
            int xl = x0 - r, xr = x0 + r;
            for (int yy = y0 - r + 1; yy <= y0 + r - 1; ++yy) { visit(yy, xl); visit(yy, xr); }
        }

        unsigned long long keys[4] = { b0, b1, b2, b3 };
        #pragma unroll
        for (int i = 0; i < 4; ++i) {
            ridx[i] = (unsigned int)(keys[i] & 0xFFFFu);
            rd2[i]  = (unsigned int)(keys[i] >> 16);
        }
    }

    // Weighted by distance (as in reference), in top_k order.
    float num = 0.0f, den = 0.0f;
    #pragma unroll
    for (int i = 0; i < 4; ++i) {
        float dist = sqrtf((float)rd2[i]) * (1.0f / 256.0f);  // == sqrt(d2/65536)
        num += __ldg(&img[ridx[i]]) * dist;
        den += dist;
    }
    out[c * NPIX + pix] = num / den;
}

extern "C" void kernel_launch(void* const* d_in, const int* in_sizes, int n_in,
                              void* d_out, int out_size) {
    const float* coded  = (const float*)d_in[0];   // [1,1,256,256]
    const int*   lookup = (const int*)d_in[1];     // [256,256]
    float* out = (float*)d_out;                    // [1,8,256,256]

    build_masks_kernel<<<SZ, SZ>>>(lookup);
    dim3 grid(SZ, NCH);
    knn_fill_kernel<<<grid, SZ>>>(coded, lookup, out);
}

// round 6
// speedup vs baseline: 1.3371x; 1.3371x over previous
#include <cuda_runtime.h>

#define SZ 256
#define NCH 8
#define NPIX (SZ*SZ)
#define WPR (SZ/32)   // words per row = 8
#define SEEDY 3       // seed rows |dy| <= 3
#define SEEDX 7       // seed width |dx| <= 7

// Per-channel occupancy bitmasks: 8 channels x 256 rows x 8 words = 64KB
__device__ unsigned int g_maskbits[NCH * SZ * WPR];

__global__ void build_masks_kernel(const int* __restrict__ lookup) {
    int y = blockIdx.x;
    int x = threadIdx.x;
    int v = lookup[y * SZ + x];
    int w = x >> 5;
    #pragma unroll
    for (int c = 0; c < NCH; ++c) {
        unsigned int mk = __ballot_sync(0xFFFFFFFFu, v == c + 1);
        if ((x & 31) == 0)
            g_maskbits[(c * SZ + y) * WPR + w] = mk;
    }
}

__global__ __launch_bounds__(256, 8) void knn_fill_kernel(
    const float* __restrict__ img, float* __restrict__ out)
{
    const int c  = blockIdx.y;   // channel 0..7
    const int y0 = blockIdx.x;   // row
    const int x0 = threadIdx.x;  // col

    __shared__ unsigned int m[SZ * WPR];  // 8KB channel bitmask
    #pragma unroll
    for (int i = 0; i < 8; ++i)
        m[i * 256 + threadIdx.x] = g_maskbits[c * SZ * WPR + i * 256 + threadIdx.x];
    __syncthreads();

    const int pix = y0 * SZ + x0;

    // Filled pixel: read bit from smem mask (no global lookup load)
    if ((m[(y0 << 3) + (x0 >> 5)] >> (x0 & 31)) & 1u) {
        out[c * NPIX + pix] = __ldg(&img[pix]);
        return;
    }

    // Top-4 as 32-bit keys (d2<<16)|idx; valid while d2 < 2^16 (true here: d2<=~98
    // in seed, and continuation only inserts d2 <= B <= 98). Ascending == top_k
    // order (smallest d2, ties -> smallest flat idx).
    unsigned int k0 = ~0u, k1 = ~0u, k2 = ~0u, k3 = ~0u;

    auto ins32 = [&](unsigned int key) {
        if (key < k3) {
            k3 = key;
            if (k3 < k2) {
                unsigned int t = k2; k2 = k3; k3 = t;
                if (k2 < k1) {
                    t = k1; k1 = k2; k2 = t;
                    if (k1 < k0) { t = k0; k0 = k1; k1 = t; }
                }
            }
        }
    };

    // Word-parallel scan of bits x in [lo,hi] of row yy
    auto scan_row = [&](int yy, int lo, int hi) {
        if ((unsigned)yy >= SZ) return;
        lo = lo < 0 ? 0 : lo;
        hi = hi > SZ - 1 ? SZ - 1 : hi;
        const int dy = yy - y0;
        const unsigned int base =
            ((unsigned int)(dy * dy) << 16) + (unsigned int)(yy << 8);
        const int wl = lo >> 5, wh = hi >> 5;
        const unsigned int mlo = 0xFFFFFFFFu << (lo & 31);
        const unsigned int mhi = 0xFFFFFFFFu >> (31 - (hi & 31));
        const unsigned int* row = &m[yy << 3];
        for (int w = wl; w <= wh; ++w) {
            unsigned int word = row[w];
            if (w == wl) word &= mlo;
            if (w == wh) word &= mhi;
            int xb = w << 5;
            while (word) {
                int b = __ffs(word) - 1;
                word &= word - 1;
                int x = xb + b, dx = x - x0;
                ins32(base + ((unsigned int)(dx * dx) << 16) + x);
            }
        }
    };

    // ---- Seed: rows |dy|<=3, width |dx|<=7 (no pruning; ~13 candidates) ----
    for (int yy = y0 - SEEDY; yy <= y0 + SEEDY; ++yy)
        scan_row(yy, x0 - SEEDX, x0 + SEEDX);

    bool exact = (k3 != ~0u);

    // ---- Continuation: rows |dy| >= 4, width floor(sqrt(B - dy^2)) inclusive.
    // Skipped cells have d2 > B (strict), so pruning is exact incl. ties. ----
    if (exact) {
        for (int dy = SEEDY + 1; dy < SZ; ++dy) {
            unsigned int B = k3 >> 16;
            unsigned int dy2 = (unsigned int)(dy * dy);
            if (dy2 > B) break;
            int rem = (int)(B - dy2);
            int u = __float2int_rd(sqrtf((float)rem));
            if ((u + 1) * (u + 1) <= rem) ++u;   // exact floor(sqrt(rem))
            if (u * u > rem) --u;
            scan_row(y0 - dy, x0 - u, x0 + u);
            scan_row(y0 + dy, x0 - u, x0 + u);
        }
        // Seed rows were truncated at |dx|=7: skipped cells there have
        // d2 >= 64 (+dy^2). Exact iff final d2_4 < 64 (strict, ties safe).
        exact = (k3 >> 16) < 64u;
    }

    unsigned int ridx[4], rd2[4];

    if (exact) {
        ridx[0] = k0 & 0xFFFFu; rd2[0] = k0 >> 16;
        ridx[1] = k1 & 0xFFFFu; rd2[1] = k1 >> 16;
        ridx[2] = k2 & 0xFFFFu; rd2[2] = k2 >> 16;
        ridx[3] = k3 & 0xFFFFu; rd2[3] = k3 >> 16;
    } else {
        // ---- Extremely rare exact fallback: expanding Chebyshev rings ----
        unsigned long long b0 = ~0ULL, b1 = ~0ULL, b2 = ~0ULL, b3 = ~0ULL;
        int found = 0;

        auto visit = [&](int yy, int xx) {
            if ((unsigned)yy >= SZ || (unsigned)xx >= SZ) return;
            unsigned int word = m[(yy << 3) + (xx >> 5)];
            if ((word >> (xx & 31)) & 1u) {
                int dy = yy - y0, dx = xx - x0;
                unsigned int d2 = (unsigned int)(dy * dy + dx * dx);
                unsigned long long key =
                    ((unsigned long long)d2 << 16) | (unsigned int)((yy << 8) + xx);
                ++found;
                if (key < b3) {
                    b3 = key;
                    if (b3 < b2) {
                        unsigned long long t = b2; b2 = b3; b3 = t;
                        if (b2 < b1) {
                            t = b1; b1 = b2; b2 = t;
                            if (b1 < b0) { t = b0; b0 = b1; b1 = t; }
                        }
                    }
                }
            }
        };

        for (int r = 1; r < SZ; ++r) {
            if (found >= 4 && (unsigned int)(r * r) > (unsigned int)(b3 >> 16)) break;
            int yt = y0 - r, yb = y0 + r;
            for (int xx = x0 - r; xx <= x0 + r; ++xx) { visit(yt, xx); visit(yb, xx); }
            int xl = x0 - r, xr = x0 + r;
            for (int yy = y0 - r + 1; yy <= y0 + r - 1; ++yy) { visit(yy, xl); visit(yy, xr); }
        }

        unsigned long long keys[4] = { b0, b1, b2, b3 };
        #pragma unroll
        for (int i = 0; i < 4; ++i) {
            ridx[i] = (unsigned int)(keys[i] & 0xFFFFu);
            rd2[i]  = (unsigned int)(keys[i] >> 16);
        }
    }

    // Weighted by distance (as in reference), in top_k order.
    float num = 0.0f, den = 0.0f;
    #pragma unroll
    for (int i = 0; i < 4; ++i) {
        float dist = sqrtf((float)rd2[i]) * (1.0f / 256.0f);  // == sqrt(d2/65536)
        num += __ldg(&img[ridx[i]]) * dist;
        den += dist;
    }
    out[c * NPIX + pix] = num / den;
}

extern "C" void kernel_launch(void* const* d_in, const int* in_sizes, int n_in,
                              void* d_out, int out_size) {
    const float* coded  = (const float*)d_in[0];   // [1,1,256,256]
    const int*   lookup = (const int*)d_in[1];     // [256,256]
    float* out = (float*)d_out;                    // [1,8,256,256]

    build_masks_kernel<<<SZ, SZ>>>(lookup);
    dim3 grid(SZ, NCH);
    knn_fill_kernel<<<grid, SZ>>>(coded, out);
}